// round 5
// baseline (speedup 1.0000x reference)
#include <cuda_runtime.h>
#include <cuda_fp16.h>
#include <cstdint>

// Single fused per-tile kernel: 64 tokens per CTA own the full chain.
//   phase0: out = x + res^T (fp32 shortcut, gmem); H = half(LN(..)) -> smem
//   phase1: hd = relu(H @ Wd^T + bd) -> smem      (Wd streamed, cp.async x2)
//   phase2: out = shortcut + hd @ Wu^T + bup      (Wu + shortcut streamed)
// Plus a tiny convert_w kernel (Wd,Wu fp32 -> half scratch).

#define NTOK 32768
#define DDIM 1024
#define BN   128
#define THREADS 256

__device__ __align__(16) __half g_Wd[BN * DDIM];
__device__ __align__(16) __half g_Wu[DDIM * BN];

// ---------------- smem layout (bytes) ----------------
// shd   : half[64*136]                      17408
// sbd   : float[128]                          512
// sbup  : float[1024]                        4096
// union R:
//   phase1: sH half[64*1032] (132096) + sWd half[2*128*72] (36864) = 168960
//   phase2: sWu half[2*128*136] (69632) + sout float[2*64*132] (67584) = 137216
static constexpr int OFF_SHD  = 0;
static constexpr int OFF_SBD  = OFF_SHD + 64 * 136 * 2;     // 17408
static constexpr int OFF_SBUP = OFF_SBD + 128 * 4;          // 17920
static constexpr int OFF_R    = OFF_SBUP + 1024 * 4;        // 22016
static constexpr int OFF_SH   = OFF_R;                      // phase1 H
static constexpr int OFF_SWD  = OFF_SH + 64 * 1032 * 2;     // phase1 Wd stages
static constexpr int OFF_SWU  = OFF_R;                      // phase2 Wu stages
static constexpr int OFF_SOUT = OFF_SWU + 2 * 128 * 136 * 2;
static constexpr int SMEM_BYTES = OFF_R + 168960;           // 190976

static constexpr int H_ST  = 1032;   // sH row stride (halves)
static constexpr int WD_ST = 72;     // Wd stage row stride (halves)
static constexpr int WD_STG = 128 * WD_ST;
static constexpr int WU_ST = 136;    // Wu / hd row stride (halves)
static constexpr int WU_STG = 128 * WU_ST;
static constexpr int OUT_ST = 132;   // sout row stride (floats)
static constexpr int OUT_STG = 64 * OUT_ST;

__device__ __forceinline__ void mma16(float* c, const uint32_t* a, const uint32_t* b) {
    asm volatile(
        "mma.sync.aligned.m16n8k16.row.col.f32.f16.f16.f32 "
        "{%0,%1,%2,%3}, {%4,%5,%6,%7}, {%8,%9}, {%0,%1,%2,%3};\n"
        : "+f"(c[0]), "+f"(c[1]), "+f"(c[2]), "+f"(c[3])
        : "r"(a[0]), "r"(a[1]), "r"(a[2]), "r"(a[3]), "r"(b[0]), "r"(b[1]));
}

__device__ __forceinline__ void ldsm4(uint32_t* r, const __half* p) {
    uint32_t a = (uint32_t)__cvta_generic_to_shared(p);
    asm volatile("ldmatrix.sync.aligned.m8n8.x4.shared.b16 {%0,%1,%2,%3}, [%4];\n"
                 : "=r"(r[0]), "=r"(r[1]), "=r"(r[2]), "=r"(r[3]) : "r"(a));
}

__device__ __forceinline__ void cp16(void* dst_sm, const void* src) {
    uint32_t a = (uint32_t)__cvta_generic_to_shared(dst_sm);
    asm volatile("cp.async.cg.shared.global [%0], [%1], 16;\n" :: "r"(a), "l"(src));
}
__device__ __forceinline__ void cp_commit() {
    asm volatile("cp.async.commit_group;\n");
}
template <int N>
__device__ __forceinline__ void cp_wait() {
    asm volatile("cp.async.wait_group %0;\n" :: "n"(N));
}

// ------------------------------------------------------------------ kernel 1
__global__ void convert_w(const float* __restrict__ Wd, const float* __restrict__ Wu) {
    const int i = blockIdx.x * blockDim.x + threadIdx.x; // 131072 threads
    g_Wd[i] = __float2half_rn(Wd[i]);
    g_Wu[i] = __float2half_rn(Wu[i]);
}

// ------------------------------------------------------------------ fused
__global__ __launch_bounds__(THREADS, 1) void fused_tile(
    const float* __restrict__ x, const float* __restrict__ res,
    const float* __restrict__ gamma, const float* __restrict__ beta,
    const float* __restrict__ bd, const float* __restrict__ bup,
    float* __restrict__ out)
{
    extern __shared__ char smem[];
    __half* shd  = (__half*)(smem + OFF_SHD);
    float*  sbd  = (float*)(smem + OFF_SBD);
    float*  sbup = (float*)(smem + OFF_SBUP);
    __half* sH   = (__half*)(smem + OFF_SH);
    __half* sWd  = (__half*)(smem + OFF_SWD);
    __half* sWu  = (__half*)(smem + OFF_SWU);
    float*  sout = (float*)(smem + OFF_SOUT);

    const int tid  = threadIdx.x;
    const int lane = tid & 31, warp = tid >> 5;
    const int t0   = blockIdx.x * 64;

    const int mw = warp >> 2, nw = warp & 3;
    const int gid = lane >> 2, tig = lane & 3;
    const int a_row = (lane & 7) + ((lane >> 3) & 1) * 8;
    const int a_kof = (lane >> 4) * 8;
    const int b_row = (lane & 7) + (lane >> 4) * 8;
    const int b_kof = ((lane >> 3) & 1) * 8;

    // ---------------- phase 0: residual add + LN -> sH, shortcut -> out ------
    for (int i = tid; i < 128; i += THREADS) sbd[i] = bd[i];
    for (int i = tid; i < 1024; i += THREADS) sbup[i] = bup[i];

    const float4* g4 = (const float4*)gamma;
    const float4* b4 = (const float4*)beta;
    #pragma unroll 1
    for (int tt = 0; tt < 8; ++tt) {
        const int row = warp * 8 + tt;
        const int n = t0 + row;
        const int s = n >> 3, b = n & 7;
        const float4* xr = (const float4*)(x + (size_t)n * DDIM);
        const float4* rr = (const float4*)(res + ((size_t)b * 4096 + s) * DDIM);
        float4* orow = (float4*)(out + (size_t)n * DDIM);

        float4 v[8];
        float sum = 0.f, sq = 0.f;
        #pragma unroll
        for (int i = 0; i < 8; ++i) {
            const int k = i * 32 + lane;
            const float4 a = xr[k], r = rr[k];
            float4 t;
            t.x = a.x + r.x; t.y = a.y + r.y; t.z = a.z + r.z; t.w = a.w + r.w;
            v[i] = t;
            orow[k] = t;
            sum += t.x + t.y + t.z + t.w;
            sq  += t.x * t.x + t.y * t.y + t.z * t.z + t.w * t.w;
        }
        #pragma unroll
        for (int o = 16; o > 0; o >>= 1) {
            sum += __shfl_xor_sync(0xffffffffu, sum, o);
            sq  += __shfl_xor_sync(0xffffffffu, sq, o);
        }
        const float mu   = sum * (1.f / 1024.f);
        const float var  = sq * (1.f / 1024.f) - mu * mu;
        const float rstd = rsqrtf(var + 1e-5f);

        #pragma unroll
        for (int i = 0; i < 8; ++i) {
            const int k = i * 32 + lane;
            const float4 g = g4[k], be = b4[k];
            __half2 h0 = __floats2half2_rn((v[i].x - mu) * rstd * g.x + be.x,
                                           (v[i].y - mu) * rstd * g.y + be.y);
            __half2 h1 = __floats2half2_rn((v[i].z - mu) * rstd * g.z + be.z,
                                           (v[i].w - mu) * rstd * g.w + be.w);
            uint2 u;
            u.x = *(uint32_t*)&h0;
            u.y = *(uint32_t*)&h1;
            *(uint2*)(sH + (size_t)row * H_ST + k * 4) = u;
        }
    }
    __syncthreads();

    // ---------------- phase 1: hd = relu(H @ Wd^T + bd) -> shd ---------------
    auto issueWd = [&](int st, int kc) {
        __half* sg = sWd + st * WD_STG;
        const int kg0 = kc * 64;
        #pragma unroll
        for (int p = 0; p < 4; ++p) {           // 128 rows x 64 halves
            const int idx = p * THREADS + tid;
            const int nn = idx >> 3, j = (idx & 7) * 8;
            cp16(sg + nn * WD_ST + j, g_Wd + (size_t)nn * DDIM + kg0 + j);
        }
        cp_commit();
    };

    float acc[2][4][4];
    #pragma unroll
    for (int i = 0; i < 2; ++i)
        #pragma unroll
        for (int j = 0; j < 4; ++j)
            #pragma unroll
            for (int q = 0; q < 4; ++q) acc[i][j][q] = 0.f;

    issueWd(0, 0);
    issueWd(1, 1);

    #pragma unroll 1
    for (int kc = 0; kc < 16; ++kc) {
        if (kc == 15) cp_wait<0>(); else cp_wait<1>();
        __syncthreads();
        const __half* sb = sWd + (kc & 1) * WD_STG;
        #pragma unroll
        for (int ks = 0; ks < 4; ++ks) {
            const int kb0 = kc * 64 + ks * 16;  // into sH
            const int wk0 = ks * 16;            // into Wd stage
            uint32_t a[2][4], bf[2][4];
            #pragma unroll
            for (int mt = 0; mt < 2; ++mt)
                ldsm4(a[mt], sH + (mw * 32 + mt * 16 + a_row) * H_ST + kb0 + a_kof);
            #pragma unroll
            for (int nt2 = 0; nt2 < 2; ++nt2)
                ldsm4(bf[nt2], sb + (nw * 32 + nt2 * 16 + b_row) * WD_ST + wk0 + b_kof);
            #pragma unroll
            for (int mt = 0; mt < 2; ++mt)
                #pragma unroll
                for (int nt = 0; nt < 4; ++nt)
                    mma16(acc[mt][nt], a[mt], bf[nt >> 1] + (nt & 1) * 2);
        }
        __syncthreads();
        if (kc + 2 < 16) issueWd((kc + 2) & 1, kc + 2);
    }

    // epilogue: +bd, relu -> shd (half, stride 136)
    #pragma unroll
    for (int mt = 0; mt < 2; ++mt) {
        #pragma unroll
        for (int nt = 0; nt < 4; ++nt) {
            const int row = mw * 32 + mt * 16 + gid;
            const int col = nw * 32 + nt * 8 + 2 * tig;
            const float b0 = sbd[col], b1 = sbd[col + 1];
            const float* c = acc[mt][nt];
            __half2 h0 = __floats2half2_rn(fmaxf(c[0] + b0, 0.f), fmaxf(c[1] + b1, 0.f));
            __half2 h1 = __floats2half2_rn(fmaxf(c[2] + b0, 0.f), fmaxf(c[3] + b1, 0.f));
            *(uint32_t*)(shd + row * WU_ST + col)       = *(uint32_t*)&h0;
            *(uint32_t*)(shd + (row + 8) * WU_ST + col) = *(uint32_t*)&h1;
        }
    }
    __syncthreads();   // shd ready; sH/sWd region now dead -> reuse for phase 2

    // ---------------- phase 2: out = shortcut + hd @ Wu^T + bup --------------
    auto issueC = [&](int st, int nc) {
        __half* wg = sWu + st * WU_STG;
        #pragma unroll
        for (int p = 0; p < 8; ++p) {           // Wu: 128 rows x 128 halves
            const int idx = p * THREADS + tid;
            const int nn = idx >> 4, j = (idx & 15) * 8;
            cp16(wg + nn * WU_ST + j, g_Wu + (size_t)(nc * 128 + nn) * BN + j);
        }
        float* og = sout + st * OUT_STG;
        #pragma unroll
        for (int p = 0; p < 8; ++p) {           // shortcut: 64 rows x 128 floats
            const int idx = p * THREADS + tid;
            const int row = idx >> 5, j = (idx & 31) * 4;
            cp16(og + row * OUT_ST + j, out + (size_t)(t0 + row) * DDIM + nc * 128 + j);
        }
        cp_commit();
    };

    issueC(0, 0);
    issueC(1, 1);

    #pragma unroll 1
    for (int nc = 0; nc < 8; ++nc) {
        if (nc == 7) cp_wait<0>(); else cp_wait<1>();
        __syncthreads();
        const __half* wg = sWu + (nc & 1) * WU_STG;
        const float*  og = sout + (nc & 1) * OUT_STG;

        float a2[2][4][4];
        #pragma unroll
        for (int i = 0; i < 2; ++i)
            #pragma unroll
            for (int j = 0; j < 4; ++j)
                #pragma unroll
                for (int q = 0; q < 4; ++q) a2[i][j][q] = 0.f;

        #pragma unroll
        for (int ks = 0; ks < 8; ++ks) {
            const int kb0 = ks * 16;
            uint32_t a[2][4], bf[2][4];
            #pragma unroll
            for (int mt = 0; mt < 2; ++mt)
                ldsm4(a[mt], shd + (mw * 32 + mt * 16 + a_row) * WU_ST + kb0 + a_kof);
            #pragma unroll
            for (int nt2 = 0; nt2 < 2; ++nt2)
                ldsm4(bf[nt2], wg + (nw * 32 + nt2 * 16 + b_row) * WU_ST + kb0 + b_kof);
            #pragma unroll
            for (int mt = 0; mt < 2; ++mt)
                #pragma unroll
                for (int nt = 0; nt < 4; ++nt)
                    mma16(a2[mt][nt], a[mt], bf[nt >> 1] + (nt & 1) * 2);
        }

        // epilogue: out = shortcut(smem) + bup + gemm2
        #pragma unroll
        for (int mt = 0; mt < 2; ++mt) {
            #pragma unroll
            for (int nt = 0; nt < 4; ++nt) {
                const int row  = mw * 32 + mt * 16 + gid;
                const int col  = nw * 32 + nt * 8 + 2 * tig;
                const int gcol = nc * 128 + col;
                const float b0 = sbup[gcol], b1 = sbup[gcol + 1];
                const size_t off  = (size_t)(t0 + row) * DDIM + gcol;
                const size_t off2 = off + (size_t)8 * DDIM;
                const float* c = a2[mt][nt];
                const float2 s0 = *(const float2*)(og + row * OUT_ST + col);
                const float2 s1 = *(const float2*)(og + (row + 8) * OUT_ST + col);
                float2 o0, o1;
                o0.x = c[0] + b0 + s0.x; o0.y = c[1] + b1 + s0.y;
                o1.x = c[2] + b0 + s1.x; o1.y = c[3] + b1 + s1.y;
                *(float2*)(out + off)  = o0;
                *(float2*)(out + off2) = o1;
            }
        }
        __syncthreads();
        if (nc + 2 < 8) issueC((nc + 2) & 1, nc + 2);
    }
}

// ------------------------------------------------------------------ launch
extern "C" void kernel_launch(void* const* d_in, const int* in_sizes, int n_in,
                              void* d_out, int out_size) {
    const float* x     = (const float*)d_in[0];
    const float* res   = (const float*)d_in[1];
    const float* gamma = (const float*)d_in[2];
    const float* beta  = (const float*)d_in[3];
    const float* Wd    = (const float*)d_in[4];
    const float* bd    = (const float*)d_in[5];
    const float* Wu    = (const float*)d_in[6];
    const float* bup   = (const float*)d_in[7];
    float* out = (float*)d_out;

    static bool attr_done = false;
    if (!attr_done) {
        cudaFuncSetAttribute(fused_tile,
                             cudaFuncAttributeMaxDynamicSharedMemorySize, SMEM_BYTES);
        attr_done = true;
    }

    convert_w<<<512, 256>>>(Wd, Wu);
    fused_tile<<<512, THREADS, SMEM_BYTES>>>(x, res, gamma, beta, bd, bup, out);
}